// round 5
// baseline (speedup 1.0000x reference)
#include <cuda_runtime.h>

#define NATOMS   1500
#define NODE_DIM 128
#define HIDDEN   64
#define MUL1E    64
#define HID1E    32
#define NUM_BASIS 20
#define NB       10      // nodes per block in node_kernel
#define T        16      // edge tile side
#define NT       94      // ceil(1500/16)
#define ROWF     13500   // floats per output row: 1500*9

// Per-node packed data: a[3], b[3], coord[3], pad[3]  (48B)
__device__ __align__(16) float g_node[NATOMS * 12];

__global__ void node_kernel(
    const float* __restrict__ xs,   const float* __restrict__ xsph,
    const float* __restrict__ coord,
    const float* __restrict__ Wsi1, const float* __restrict__ Wsi2,
    const float* __restrict__ Wsj1, const float* __restrict__ Wsj2,
    const float* __restrict__ Wpi1, const float* __restrict__ Wpi2,
    const float* __restrict__ Wpj1, const float* __restrict__ Wpj2)
{
    int n0 = blockIdx.x * NB;
    int t = threadIdx.x;
    int lane = t & 31;
    int wid = t >> 5;
    __shared__ float sx[NB][NODE_DIM];
    __shared__ float sv[NB][MUL1E * 3];
    __shared__ float red[NB][4];
    __shared__ float soi[NB][3], soj[NB][3];

    for (int idx = t; idx < NB * NODE_DIM; idx += 128) {
        int nb = idx >> 7, f = idx & 127;
        sx[nb][f] = xs[(n0 + nb) * NODE_DIM + f];
    }
    for (int idx = t; idx < NB * MUL1E * 3; idx += 128) {
        int nb = idx / 192, k = idx % 192;
        sv[nb][k] = xsph[(n0 + nb) * 480 + 128 + k];
    }
    __syncthreads();

    // ---- scalar MLPs: silu(x@W1)@W2.  t<64 -> i-role, t>=64 -> j-role
    {
        const float* W1 = (t < 64) ? Wsi1 : Wsj1;
        const float* W2 = (t < 64) ? Wsi2 : Wsj2;
        int h = t & 63;
        float acc[NB];
        #pragma unroll
        for (int nb = 0; nb < NB; nb++) acc[nb] = 0.f;
        #pragma unroll 4
        for (int f = 0; f < NODE_DIM; f++) {
            float w = W1[f * HIDDEN + h];
            #pragma unroll
            for (int nb = 0; nb < NB; nb++) acc[nb] += sx[nb][f] * w;
        }
        float w2 = W2[h];
        #pragma unroll
        for (int nb = 0; nb < NB; nb++) {
            float d = acc[nb];
            float s = d / (1.f + __expf(-d)) * w2;      // silu * W2
            #pragma unroll
            for (int off = 16; off > 0; off >>= 1) s += __shfl_down_sync(0xffffffffu, s, off);
            if (lane == 0) red[nb][wid] = s;
        }
    }

    // ---- spherical MLPs: warp 0 -> i-role, warp 1 -> j-role
    if (t < 64) {
        const float* W1 = (t < 32) ? Wpi1 : Wpj1;
        const float* W2 = (t < 32) ? Wpi2 : Wpj2;
        int h = lane;
        float a0[NB], a1[NB], a2[NB];
        #pragma unroll
        for (int nb = 0; nb < NB; nb++) { a0[nb] = 0.f; a1[nb] = 0.f; a2[nb] = 0.f; }
        #pragma unroll 4
        for (int m = 0; m < MUL1E; m++) {
            float w = W1[m * HID1E + h];
            #pragma unroll
            for (int nb = 0; nb < NB; nb++) {
                a0[nb] += sv[nb][m * 3 + 0] * w;
                a1[nb] += sv[nb][m * 3 + 1] * w;
                a2[nb] += sv[nb][m * 3 + 2] * w;
            }
        }
        float w2c = W2[h];
        #pragma unroll
        for (int nb = 0; nb < NB; nb++) {
            float h0 = a0[nb] * 0.125f, h1 = a1[nb] * 0.125f, h2 = a2[nb] * 0.125f;
            float nrm = sqrtf(h0 * h0 + h1 * h1 + h2 * h2);
            float gate = 1.f / (1.f + __expf(-nrm));
            float w2 = w2c * gate;
            float o0 = h0 * w2, o1 = h1 * w2, o2 = h2 * w2;
            #pragma unroll
            for (int off = 16; off > 0; off >>= 1) {
                o0 += __shfl_down_sync(0xffffffffu, o0, off);
                o1 += __shfl_down_sync(0xffffffffu, o1, off);
                o2 += __shfl_down_sync(0xffffffffu, o2, off);
            }
            if (lane == 0) {
                float* dst = (t < 32) ? soi[nb] : soj[nb];
                dst[0] = o0; dst[1] = o1; dst[2] = o2;
            }
        }
    }
    __syncthreads();

    if (t < NB) {
        int nb = t, n = n0 + nb;
        const float inv32 = 0.17677669529663689f;   // 1/sqrt(32)
        float fa = (1.f + red[nb][0] + red[nb][1]) * inv32;
        float fb = (1.f + red[nb][2] + red[nb][3]) * inv32;
        float* gp = g_node + n * 12;
        // e3nn (y,z,x) -> (x,y,z) permutation [2,0,1], fold in gate (1+s)
        gp[0] = soi[nb][2] * fa;  gp[1] = soi[nb][0] * fa;  gp[2] = soi[nb][1] * fa;
        gp[3] = soj[nb][2] * fb;  gp[4] = soj[nb][0] * fb;  gp[5] = soj[nb][1] * fb;
        gp[6] = coord[n * 3 + 0]; gp[7] = coord[n * 3 + 1]; gp[8] = coord[n * 3 + 2];
        gp[9] = 0.f; gp[10] = 0.f; gp[11] = 0.f;
    }
}

// Symmetric tiles: block computes 16x16 (i,j) pairs of the upper triangle,
// writes the tile and (if off-diagonal) its transpose. out[j,i] = out[i,j]^T.
__global__ __launch_bounds__(256, 4)
void edge_kernel(const float* __restrict__ Wrbf, float* __restrict__ out)
{
    int b = blockIdx.x;
    // triangular decode: row ti has (NT - ti) tiles, cum(ti) = ti*NT - ti*(ti-1)/2
    int ti = (int)((2.f * NT + 1.f - sqrtf((2.f * NT + 1.f) * (2.f * NT + 1.f) - 8.f * (float)b)) * 0.5f);
    if (ti < 0) ti = 0; if (ti > NT - 1) ti = NT - 1;
    while (ti * NT - ti * (ti - 1) / 2 > b) ti--;
    while ((ti + 1) * NT - (ti + 1) * ti / 2 <= b) ti++;
    int tj = ti + (b - (ti * NT - ti * (ti - 1) / 2));

    int t  = threadIdx.x;
    int tx = t & 15;        // j within tile
    int ty = t >> 4;        // i within tile

    __shared__ float gi[T][12];
    __shared__ float gj[T][12];
    __shared__ float sW[NUM_BASIS];
    __shared__ float sbuf[T * T * 9];   // [ii][jj][9]

    if (t < NUM_BASIS) sW[t] = Wrbf[t];
    for (int u = t; u < T * 12; u += 256) {          // 192 elems, all threads
        int n = ti * T + u / 12;
        gi[u / 12][u % 12] = (n < NATOMS) ? g_node[n * 12 + u % 12] : 0.f;
    }
    for (int u = t; u < T * 12; u += 256) {
        int n = tj * T + u / 12;
        gj[u / 12][u % 12] = (n < NATOMS) ? g_node[n * 12 + u % 12] : 0.f;
    }
    __syncthreads();

    int vi = NATOMS - ti * T; if (vi > T) vi = T;
    int vj = NATOMS - tj * T; if (vj > T) vj = T;

    {
        float* s = sbuf + (ty * T + tx) * 9;
        if (ty < vi && tx < vj) {
            float dx = gi[ty][6] - gj[tx][6];
            float dy = gi[ty][7] - gj[tx][7];
            float dz = gi[ty][8] - gj[tx][8];
            float d = sqrtf(dx * dx + dy * dy + dz * dz);

            const float delta = 5.0f / 19.0f;
            const float coeff = -0.5f / (delta * delta);
            int k0 = __float2int_rn(d * (19.0f / 5.0f));
            float fc = 0.f;
            #pragma unroll
            for (int kk = 0; kk < 11; kk++) {
                int k = k0 - 5 + kk;
                float w = (k >= 0 && k < NUM_BASIS) ? sW[k] : 0.f;
                float u = d - (float)k * delta;
                fc += w * __expf(coeff * u * u);
            }
            float h = 0.5f * fc;

            float ai0 = gi[ty][0] * h, ai1 = gi[ty][1] * h, ai2 = gi[ty][2] * h;
            float bi0 = gi[ty][3] * h, bi1 = gi[ty][4] * h, bi2 = gi[ty][5] * h;
            float aj0 = gj[tx][0], aj1 = gj[tx][1], aj2 = gj[tx][2];
            float bj0 = gj[tx][3], bj1 = gj[tx][4], bj2 = gj[tx][5];

            s[0] = ai0 * bj0 + bi0 * aj0;
            s[1] = ai0 * bj1 + bi0 * aj1;
            s[2] = ai0 * bj2 + bi0 * aj2;
            s[3] = ai1 * bj0 + bi1 * aj0;
            s[4] = ai1 * bj1 + bi1 * aj1;
            s[5] = ai1 * bj2 + bi1 * aj2;
            s[6] = ai2 * bj0 + bi2 * aj0;
            s[7] = ai2 * bj1 + bi2 * aj1;
            s[8] = ai2 * bj2 + bi2 * aj2;
        } else {
            #pragma unroll
            for (int c = 0; c < 9; c++) s[c] = 0.f;
        }
    }
    __syncthreads();

    // Direct tile: row i = ti*T+ii gets vj*9 contiguous floats at (i*1500 + tj*T)*9
    for (int idx = t; idx < T * T * 9; idx += 256) {
        int ii = idx / (T * 9), f = idx % (T * 9);
        if (ii < vi && f < vj * 9)
            out[(size_t)(ti * T + ii) * ROWF + (size_t)tj * T * 9 + f] = sbuf[ii * T * 9 + f];
    }

    // Transpose tile (off-diagonal only): out[j,i][p,q] = sbuf[i,j][q,p]
    if (ti != tj) {
        for (int idx = t; idx < T * T * 9; idx += 256) {
            int jj = idx / (T * 9), g = idx % (T * 9);
            if (jj < vj && g < vi * 9) {
                int ii = g / 9, cc = g % 9;
                out[(size_t)(tj * T + jj) * ROWF + (size_t)ti * T * 9 + g] =
                    sbuf[(ii * T + jj) * 9 + (cc % 3) * 3 + cc / 3];
            }
        }
    }
}

extern "C" void kernel_launch(void* const* d_in, const int* in_sizes, int n_in,
                              void* d_out, int out_size)
{
    const float* xs    = (const float*)d_in[0];
    const float* xsph  = (const float*)d_in[1];
    const float* coord = (const float*)d_in[2];
    // d_in[3] = fc_edge_index (int32, full graph i-major) — structure fixed, unused
    const float* Wsi1 = (const float*)d_in[4];
    const float* Wsi2 = (const float*)d_in[5];
    const float* Wsj1 = (const float*)d_in[6];
    const float* Wsj2 = (const float*)d_in[7];
    const float* Wpi1 = (const float*)d_in[8];
    const float* Wpi2 = (const float*)d_in[9];
    const float* Wpj1 = (const float*)d_in[10];
    const float* Wpj2 = (const float*)d_in[11];
    const float* Wrbf = (const float*)d_in[12];
    float* out = (float*)d_out;

    node_kernel<<<NATOMS / NB, 128>>>(xs, xsph, coord,
                                      Wsi1, Wsi2, Wsj1, Wsj2,
                                      Wpi1, Wpi2, Wpj1, Wpj2);

    int nblocks = NT * (NT + 1) / 2;   // 4465 upper-triangle tiles
    edge_kernel<<<nblocks, 256>>>(Wrbf, out);
}

// round 7
// speedup vs baseline: 2.1438x; 2.1438x over previous
#include <cuda_runtime.h>

#define NATOMS   1500
#define NODE_DIM 128
#define HIDDEN   64
#define MUL1E    64
#define HID1E    32
#define NUM_BASIS 20
#define NB       4       // nodes per block in node_kernel
#define T        16      // edge tile side
#define NT       94      // ceil(1500/16)
#define ROWF     13500   // floats per output row: 1500*9
#define BSTRIDE  148     // padded row stride for transposed buffer (floats)

// Per-node packed data: a[3], b[3], coord[3], pad[3]  (48B)
__device__ __align__(16) float g_node[NATOMS * 12];

__global__ void node_kernel(
    const float* __restrict__ xs,   const float* __restrict__ xsph,
    const float* __restrict__ coord,
    const float* __restrict__ Wsi1, const float* __restrict__ Wsi2,
    const float* __restrict__ Wsj1, const float* __restrict__ Wsj2,
    const float* __restrict__ Wpi1, const float* __restrict__ Wpi2,
    const float* __restrict__ Wpj1, const float* __restrict__ Wpj2)
{
    int n0 = blockIdx.x * NB;
    int t = threadIdx.x;
    int lane = t & 31;
    int wid = t >> 5;
    __shared__ float sx[NB][NODE_DIM];
    __shared__ float sv[NB][MUL1E * 3];
    __shared__ float red[NB][4];
    __shared__ float soi[NB][3], soj[NB][3];

    for (int idx = t; idx < NB * NODE_DIM; idx += 128) {
        int nb = idx >> 7, f = idx & 127;
        sx[nb][f] = xs[(n0 + nb) * NODE_DIM + f];
    }
    for (int idx = t; idx < NB * MUL1E * 3; idx += 128) {
        int nb = idx / 192, k = idx % 192;
        sv[nb][k] = xsph[(n0 + nb) * 480 + 128 + k];
    }
    __syncthreads();

    // ---- scalar MLPs: silu(x@W1)@W2.  t<64 -> i-role, t>=64 -> j-role
    {
        const float* W1 = (t < 64) ? Wsi1 : Wsj1;
        const float* W2 = (t < 64) ? Wsi2 : Wsj2;
        int h = t & 63;
        float acc[NB];
        #pragma unroll
        for (int nb = 0; nb < NB; nb++) acc[nb] = 0.f;
        #pragma unroll 8
        for (int f = 0; f < NODE_DIM; f++) {
            float w = W1[f * HIDDEN + h];
            #pragma unroll
            for (int nb = 0; nb < NB; nb++) acc[nb] += sx[nb][f] * w;
        }
        float w2 = W2[h];
        #pragma unroll
        for (int nb = 0; nb < NB; nb++) {
            float d = acc[nb];
            float s = d / (1.f + __expf(-d)) * w2;      // silu * W2
            #pragma unroll
            for (int off = 16; off > 0; off >>= 1) s += __shfl_down_sync(0xffffffffu, s, off);
            if (lane == 0) red[nb][wid] = s;
        }
    }

    // ---- spherical MLPs: warp 0 -> i-role, warp 1 -> j-role
    if (t < 64) {
        const float* W1 = (t < 32) ? Wpi1 : Wpj1;
        const float* W2 = (t < 32) ? Wpi2 : Wpj2;
        int h = lane;
        float a0[NB], a1[NB], a2[NB];
        #pragma unroll
        for (int nb = 0; nb < NB; nb++) { a0[nb] = 0.f; a1[nb] = 0.f; a2[nb] = 0.f; }
        #pragma unroll 8
        for (int m = 0; m < MUL1E; m++) {
            float w = W1[m * HID1E + h];
            #pragma unroll
            for (int nb = 0; nb < NB; nb++) {
                a0[nb] += sv[nb][m * 3 + 0] * w;
                a1[nb] += sv[nb][m * 3 + 1] * w;
                a2[nb] += sv[nb][m * 3 + 2] * w;
            }
        }
        float w2c = W2[h];
        #pragma unroll
        for (int nb = 0; nb < NB; nb++) {
            float h0 = a0[nb] * 0.125f, h1 = a1[nb] * 0.125f, h2 = a2[nb] * 0.125f;
            float nrm = sqrtf(h0 * h0 + h1 * h1 + h2 * h2);
            float gate = 1.f / (1.f + __expf(-nrm));
            float w2 = w2c * gate;
            float o0 = h0 * w2, o1 = h1 * w2, o2 = h2 * w2;
            #pragma unroll
            for (int off = 16; off > 0; off >>= 1) {
                o0 += __shfl_down_sync(0xffffffffu, o0, off);
                o1 += __shfl_down_sync(0xffffffffu, o1, off);
                o2 += __shfl_down_sync(0xffffffffu, o2, off);
            }
            if (lane == 0) {
                float* dst = (t < 32) ? soi[nb] : soj[nb];
                dst[0] = o0; dst[1] = o1; dst[2] = o2;
            }
        }
    }
    __syncthreads();

    if (t < NB) {
        int nb = t, n = n0 + nb;
        const float inv32 = 0.17677669529663689f;   // 1/sqrt(32)
        float fa = (1.f + red[nb][0] + red[nb][1]) * inv32;
        float fb = (1.f + red[nb][2] + red[nb][3]) * inv32;
        float* gp = g_node + n * 12;
        // e3nn (y,z,x) -> (x,y,z) permutation [2,0,1], fold in gate (1+s)
        gp[0] = soi[nb][2] * fa;  gp[1] = soi[nb][0] * fa;  gp[2] = soi[nb][1] * fa;
        gp[3] = soj[nb][2] * fb;  gp[4] = soj[nb][0] * fb;  gp[5] = soj[nb][1] * fb;
        gp[6] = coord[n * 3 + 0]; gp[7] = coord[n * 3 + 1]; gp[8] = coord[n * 3 + 2];
        gp[9] = 0.f; gp[10] = 0.f; gp[11] = 0.f;
    }
}

// Symmetric 16x16 tiles over the upper triangle. Each thread computes one 3x3
// block and writes it in both layouts (direct + transposed) to smem; output
// copies are then pure linear float4 streams (no div/mod).
__global__ __launch_bounds__(256)
void edge_kernel(const float* __restrict__ Wrbf, float* __restrict__ out)
{
    int b = blockIdx.x;
    // triangular decode (once per block)
    int ti = (int)((2.f * NT + 1.f - sqrtf((2.f * NT + 1.f) * (2.f * NT + 1.f) - 8.f * (float)b)) * 0.5f);
    if (ti < 0) ti = 0; if (ti > NT - 1) ti = NT - 1;
    while (ti * NT - ti * (ti - 1) / 2 > b) ti--;
    while ((ti + 1) * NT - (ti + 1) * ti / 2 <= b) ti++;
    int tj = ti + (b - (ti * NT - ti * (ti - 1) / 2));

    int t  = threadIdx.x;
    int tx = t & 15;        // j within tile
    int ty = t >> 4;        // i within tile

    __shared__ __align__(16) float sbufA[T * T * 9];      // [ii][jj*9+c], row stride 144
    __shared__ __align__(16) float sbufB[T * BSTRIDE];    // [jj][ii*9+cT], row stride 148
    __shared__ float gi[T][12];
    __shared__ float gj[T][12];
    __shared__ float sW[NUM_BASIS];

    if (t < NUM_BASIS) sW[t] = Wrbf[t];
    // Two INDEPENDENT loads (overlapping thread ranges, no else!)
    if (t < T * 12) {                       // threads 0..191 -> gi
        int n = ti * T + t / 12;
        gi[t / 12][t % 12] = (n < NATOMS) ? g_node[n * 12 + t % 12] : 0.f;
    }
    if (t >= 64) {                          // threads 64..255 -> gj[0..191]
        int u = t - 64;
        int n = tj * T + u / 12;
        gj[u / 12][u % 12] = (n < NATOMS) ? g_node[n * 12 + u % 12] : 0.f;
    }
    __syncthreads();

    int vi = NATOMS - ti * T; if (vi > T) vi = T;
    int vj = NATOMS - tj * T; if (vj > T) vj = T;
    bool offdiag = (ti != tj);

    if (ty < vi && tx < vj) {
        float dx = gi[ty][6] - gj[tx][6];
        float dy = gi[ty][7] - gj[tx][7];
        float dz = gi[ty][8] - gj[tx][8];
        float d = sqrtf(dx * dx + dy * dy + dz * dz);

        const float delta = 5.0f / 19.0f;
        const float coeff = -0.5f / (delta * delta);
        int k0 = __float2int_rn(d * (19.0f / 5.0f));
        float fc = 0.f;
        #pragma unroll
        for (int kk = 0; kk < 11; kk++) {
            int k = k0 - 5 + kk;
            float w = (k >= 0 && k < NUM_BASIS) ? sW[k] : 0.f;
            float u = d - (float)k * delta;
            fc += w * __expf(coeff * u * u);
        }
        float h = 0.5f * fc;

        float ai0 = gi[ty][0] * h, ai1 = gi[ty][1] * h, ai2 = gi[ty][2] * h;
        float bi0 = gi[ty][3] * h, bi1 = gi[ty][4] * h, bi2 = gi[ty][5] * h;
        float aj0 = gj[tx][0], aj1 = gj[tx][1], aj2 = gj[tx][2];
        float bj0 = gj[tx][3], bj1 = gj[tx][4], bj2 = gj[tx][5];

        float m00 = ai0 * bj0 + bi0 * aj0;
        float m01 = ai0 * bj1 + bi0 * aj1;
        float m02 = ai0 * bj2 + bi0 * aj2;
        float m10 = ai1 * bj0 + bi1 * aj0;
        float m11 = ai1 * bj1 + bi1 * aj1;
        float m12 = ai1 * bj2 + bi1 * aj2;
        float m20 = ai2 * bj0 + bi2 * aj0;
        float m21 = ai2 * bj1 + bi2 * aj1;
        float m22 = ai2 * bj2 + bi2 * aj2;

        float* a = sbufA + ty * (T * 9) + tx * 9;
        a[0] = m00; a[1] = m01; a[2] = m02;
        a[3] = m10; a[4] = m11; a[5] = m12;
        a[6] = m20; a[7] = m21; a[8] = m22;

        if (offdiag) {
            float* bq = sbufB + tx * BSTRIDE + ty * 9;   // transposed block
            bq[0] = m00; bq[1] = m10; bq[2] = m20;
            bq[3] = m01; bq[4] = m11; bq[5] = m21;
            bq[6] = m02; bq[7] = m12; bq[8] = m22;
        }
    }
    __syncthreads();

    // Direct tile: row ii -> vj*9 floats at out[(ti*T+ii)*ROWF + tj*T*9]
    {
        int row = ty, c16 = tx;
        if (row < vi) {
            int w4 = (vj * 9) >> 2;    // vj in {16,12} -> divisible by 4
            const float4* src = (const float4*)(sbufA + row * (T * 9));
            float4* dst = (float4*)(out + (size_t)(ti * T + row) * ROWF + (size_t)tj * T * 9);
            #pragma unroll
            for (int c = c16; c < 36; c += 16)
                if (c < w4) dst[c] = src[c];
        }
    }

    // Transposed tile: row jj -> vi*9 floats at out[(tj*T+jj)*ROWF + ti*T*9]
    if (offdiag) {
        int row = ty, c16 = tx;
        if (row < vj) {
            int w4 = (vi * 9) >> 2;
            const float4* src = (const float4*)(sbufB + row * BSTRIDE);
            float4* dst = (float4*)(out + (size_t)(tj * T + row) * ROWF + (size_t)ti * T * 9);
            #pragma unroll
            for (int c = c16; c < 36; c += 16)
                if (c < w4) dst[c] = src[c];
        }
    }
}

extern "C" void kernel_launch(void* const* d_in, const int* in_sizes, int n_in,
                              void* d_out, int out_size)
{
    const float* xs    = (const float*)d_in[0];
    const float* xsph  = (const float*)d_in[1];
    const float* coord = (const float*)d_in[2];
    // d_in[3] = fc_edge_index (int32, full graph i-major) — structure fixed, unused
    const float* Wsi1 = (const float*)d_in[4];
    const float* Wsi2 = (const float*)d_in[5];
    const float* Wsj1 = (const float*)d_in[6];
    const float* Wsj2 = (const float*)d_in[7];
    const float* Wpi1 = (const float*)d_in[8];
    const float* Wpi2 = (const float*)d_in[9];
    const float* Wpj1 = (const float*)d_in[10];
    const float* Wpj2 = (const float*)d_in[11];
    const float* Wrbf = (const float*)d_in[12];
    float* out = (float*)d_out;

    node_kernel<<<NATOMS / NB, 128>>>(xs, xsph, coord,
                                      Wsi1, Wsi2, Wsj1, Wsj2,
                                      Wpi1, Wpi2, Wpj1, Wpj2);

    int nblocks = NT * (NT + 1) / 2;   // 4465 upper-triangle tiles
    edge_kernel<<<nblocks, 256>>>(Wrbf, out);
}

// round 8
// speedup vs baseline: 2.6541x; 1.2380x over previous
#include <cuda_runtime.h>

#define NATOMS   1500
#define NODE_DIM 128
#define HIDDEN   64
#define MUL1E    64
#define HID1E    32
#define NUM_BASIS 20
#define T        16      // edge tile side
#define NT       94      // ceil(1500/16)
#define ROWF     13500   // floats per output row: 1500*9
#define BSTRIDE  148     // padded row stride for transposed buffer (floats)

// Per-node packed data: a[3], b[3], coord[3], pad[3]  (48B = 3 x float4)
__device__ __align__(16) float g_node[NATOMS * 12];

__global__ void node_kernel(
    const float* __restrict__ xs,   const float* __restrict__ xsph,
    const float* __restrict__ coord,
    const float* __restrict__ Wsi1, const float* __restrict__ Wsi2,
    const float* __restrict__ Wsj1, const float* __restrict__ Wsj2,
    const float* __restrict__ Wpi1, const float* __restrict__ Wpi2,
    const float* __restrict__ Wpj1, const float* __restrict__ Wpj2)
{
    int n = blockIdx.x;
    int t = threadIdx.x;
    int lane = t & 31;
    int wid = t >> 5;
    __shared__ float sx[NODE_DIM];
    __shared__ float sv[MUL1E * 3];
    __shared__ float red[4];        // per-warp scalar partials
    __shared__ float soi[3], soj[3];

    sx[t] = xs[n * NODE_DIM + t];
    const float* vp = xsph + n * 480 + 128;   // 1e block [64,3]
    for (int k = t; k < MUL1E * 3; k += 128) sv[k] = vp[k];
    __syncthreads();

    // ---- scalar MLPs: silu(x@W1)@W2.  threads 0..63 -> i-role, 64..127 -> j-role
    {
        const float* W1 = (t < 64) ? Wsi1 : Wsj1;
        const float* W2 = (t < 64) ? Wsi2 : Wsj2;
        int h = t & 63;
        float d = 0.f;
        #pragma unroll 16
        for (int f = 0; f < NODE_DIM; f++) d += sx[f] * W1[f * HIDDEN + h];
        float s = d / (1.f + __expf(-d));     // silu
        float v = s * W2[h];
        #pragma unroll
        for (int off = 16; off > 0; off >>= 1) v += __shfl_down_sync(0xffffffffu, v, off);
        if (lane == 0) red[wid] = v;
    }

    // ---- spherical MLPs: warp 0 -> i-role, warp 1 -> j-role (one lane per hidden h)
    if (t < 64) {
        const float* W1 = (t < 32) ? Wpi1 : Wpj1;
        const float* W2 = (t < 32) ? Wpi2 : Wpj2;
        int h = lane;
        float h0 = 0.f, h1 = 0.f, h2 = 0.f;
        #pragma unroll 16
        for (int m = 0; m < MUL1E; m++) {
            float w = W1[m * HID1E + h];
            h0 += sv[m * 3 + 0] * w;
            h1 += sv[m * 3 + 1] * w;
            h2 += sv[m * 3 + 2] * w;
        }
        h0 *= 0.125f; h1 *= 0.125f; h2 *= 0.125f;   // / sqrt(64)
        float nrm = sqrtf(h0 * h0 + h1 * h1 + h2 * h2);
        float gate = 1.f / (1.f + __expf(-nrm));    // sigmoid(|h|)
        float w2 = W2[h] * gate;
        float o0 = h0 * w2, o1 = h1 * w2, o2 = h2 * w2;
        #pragma unroll
        for (int off = 16; off > 0; off >>= 1) {
            o0 += __shfl_down_sync(0xffffffffu, o0, off);
            o1 += __shfl_down_sync(0xffffffffu, o1, off);
            o2 += __shfl_down_sync(0xffffffffu, o2, off);
        }
        if (lane == 0) {
            float* dst = (t < 32) ? soi : soj;
            dst[0] = o0; dst[1] = o1; dst[2] = o2;
        }
    }
    __syncthreads();

    if (t == 0) {
        const float inv32 = 0.17677669529663689f;   // 1/sqrt(32)
        float fa = (1.f + red[0] + red[1]) * inv32;
        float fb = (1.f + red[2] + red[3]) * inv32;
        float* gp = g_node + n * 12;
        // e3nn (y,z,x) -> (x,y,z) permutation [2,0,1], fold in gate (1+s)
        gp[0] = soi[2] * fa;  gp[1] = soi[0] * fa;  gp[2] = soi[1] * fa;
        gp[3] = soj[2] * fb;  gp[4] = soj[0] * fb;  gp[5] = soj[1] * fb;
        gp[6] = coord[n*3+0]; gp[7] = coord[n*3+1]; gp[8] = coord[n*3+2];
        gp[9] = 0.f; gp[10] = 0.f; gp[11] = 0.f;
    }
}

// Symmetric 16x16 tiles over the upper triangle; dual-layout smem staging.
__global__ __launch_bounds__(256)
void edge_kernel(const float* __restrict__ Wrbf, float* __restrict__ out)
{
    int b = blockIdx.x;
    // triangular decode (once per block)
    int ti = (int)((2.f * NT + 1.f - sqrtf((2.f * NT + 1.f) * (2.f * NT + 1.f) - 8.f * (float)b)) * 0.5f);
    if (ti < 0) ti = 0; if (ti > NT - 1) ti = NT - 1;
    while (ti * NT - ti * (ti - 1) / 2 > b) ti--;
    while ((ti + 1) * NT - (ti + 1) * ti / 2 <= b) ti++;
    int tj = ti + (b - (ti * NT - ti * (ti - 1) / 2));

    int t  = threadIdx.x;
    int tx = t & 15;        // j within tile
    int ty = t >> 4;        // i within tile

    __shared__ __align__(16) float sbufA[T * T * 9];      // [ii][jj*9+c], row stride 144
    __shared__ __align__(16) float sbufB[T * BSTRIDE];    // [jj][ii*9+cT], row stride 148
    __shared__ __align__(16) float4 gi4[T][3];
    __shared__ __align__(16) float4 gj4[T][3];
    __shared__ float sWp[33];   // zero-padded: sWp[k+4] = W[k], k in [0,20)

    if (t < 33) {
        int k = t - 4;
        sWp[t] = (k >= 0 && k < NUM_BASIS) ? Wrbf[k] : 0.f;
    }
    // vectorized cooperative tile loads: 48 float4 each, independent ranges
    if (t >= 64 && t < 112) {
        int u = t - 64;                     // 0..47
        int n = ti * T + u / 3;
        ((float4*)gi4)[u] = (n < NATOMS) ? ((const float4*)g_node)[n * 3 + u % 3]
                                         : make_float4(0.f, 0.f, 0.f, 0.f);
    }
    if (t >= 128 && t < 176) {
        int u = t - 128;
        int n = tj * T + u / 3;
        ((float4*)gj4)[u] = (n < NATOMS) ? ((const float4*)g_node)[n * 3 + u % 3]
                                         : make_float4(0.f, 0.f, 0.f, 0.f);
    }
    __syncthreads();

    int vi = NATOMS - ti * T; if (vi > T) vi = T;
    int vj = NATOMS - tj * T; if (vj > T) vj = T;
    bool offdiag = (ti != tj);

    if (ty < vi && tx < vj) {
        float4 i0 = gi4[ty][0], i1 = gi4[ty][1], i2 = gi4[ty][2];
        float4 j0 = gj4[tx][0], j1 = gj4[tx][1], j2 = gj4[tx][2];

        float dx = i1.z - j1.z, dy = i1.w - j1.w, dz = i2.x - j2.x;
        float d = sqrtf(dx * dx + dy * dy + dz * dz);

        const float delta = 5.0f / 19.0f;
        const float coeff = -0.5f / (delta * delta);
        int k0 = __float2int_rn(d * (19.0f / 5.0f));
        int k0c = min(k0, 24);
        float u0 = d - (float)(k0c - 4) * delta;   // u for kk=0
        float fc = 0.f;
        #pragma unroll
        for (int kk = 0; kk < 9; kk++) {
            float u = u0 - (float)kk * delta;
            fc += sWp[k0c + kk] * __expf(coeff * u * u);
        }
        float h = 0.5f * fc;

        float ai0 = i0.x * h, ai1 = i0.y * h, ai2 = i0.z * h;
        float bi0 = i0.w * h, bi1 = i1.x * h, bi2 = i1.y * h;
        float aj0 = j0.x, aj1 = j0.y, aj2 = j0.z;
        float bj0 = j0.w, bj1 = j1.x, bj2 = j1.y;

        float m00 = ai0 * bj0 + bi0 * aj0;
        float m01 = ai0 * bj1 + bi0 * aj1;
        float m02 = ai0 * bj2 + bi0 * aj2;
        float m10 = ai1 * bj0 + bi1 * aj0;
        float m11 = ai1 * bj1 + bi1 * aj1;
        float m12 = ai1 * bj2 + bi1 * aj2;
        float m20 = ai2 * bj0 + bi2 * aj0;
        float m21 = ai2 * bj1 + bi2 * aj1;
        float m22 = ai2 * bj2 + bi2 * aj2;

        float* a = sbufA + ty * (T * 9) + tx * 9;
        a[0] = m00; a[1] = m01; a[2] = m02;
        a[3] = m10; a[4] = m11; a[5] = m12;
        a[6] = m20; a[7] = m21; a[8] = m22;

        if (offdiag) {
            float* bq = sbufB + tx * BSTRIDE + ty * 9;   // transposed block
            bq[0] = m00; bq[1] = m10; bq[2] = m20;
            bq[3] = m01; bq[4] = m11; bq[5] = m21;
            bq[6] = m02; bq[7] = m12; bq[8] = m22;
        }
    }
    __syncthreads();

    // Direct tile: row ii -> vj*9 floats at out[(ti*T+ii)*ROWF + tj*T*9]
    if (ty < vi) {
        int w4 = (vj * 9) >> 2;    // vj in {16,12} -> divisible by 4
        const float4* src = (const float4*)(sbufA + ty * (T * 9));
        float4* dst = (float4*)(out + (size_t)(ti * T + ty) * ROWF + (size_t)tj * T * 9);
        #pragma unroll
        for (int c = tx; c < 36; c += 16)
            if (c < w4) dst[c] = src[c];
    }

    // Transposed tile: row jj -> vi*9 floats at out[(tj*T+jj)*ROWF + ti*T*9]
    if (offdiag && ty < vj) {
        int w4 = (vi * 9) >> 2;
        const float4* src = (const float4*)(sbufB + ty * BSTRIDE);
        float4* dst = (float4*)(out + (size_t)(tj * T + ty) * ROWF + (size_t)ti * T * 9);
        #pragma unroll
        for (int c = tx; c < 36; c += 16)
            if (c < w4) dst[c] = src[c];
    }
}

extern "C" void kernel_launch(void* const* d_in, const int* in_sizes, int n_in,
                              void* d_out, int out_size)
{
    const float* xs    = (const float*)d_in[0];
    const float* xsph  = (const float*)d_in[1];
    const float* coord = (const float*)d_in[2];
    // d_in[3] = fc_edge_index (int32, full graph i-major) — structure fixed, unused
    const float* Wsi1 = (const float*)d_in[4];
    const float* Wsi2 = (const float*)d_in[5];
    const float* Wsj1 = (const float*)d_in[6];
    const float* Wsj2 = (const float*)d_in[7];
    const float* Wpi1 = (const float*)d_in[8];
    const float* Wpi2 = (const float*)d_in[9];
    const float* Wpj1 = (const float*)d_in[10];
    const float* Wpj2 = (const float*)d_in[11];
    const float* Wrbf = (const float*)d_in[12];
    float* out = (float*)d_out;

    node_kernel<<<NATOMS, 128>>>(xs, xsph, coord,
                                 Wsi1, Wsi2, Wsj1, Wsj2,
                                 Wpi1, Wpi2, Wpj1, Wpj2);

    int nblocks = NT * (NT + 1) / 2;   // 4465 upper-triangle tiles
    edge_kernel<<<nblocks, 256>>>(Wrbf, out);
}